// round 1
// baseline (speedup 1.0000x reference)
#include <cuda_runtime.h>
#include <cstdint>
#include <cstddef>

// Problem constants (fixed shapes from reference):
//   x: [N=32, C=64, V=25, T=1024] fp32
//   W: [V=25, O=K*C=192, C=64]    fp32
//   A: [K=3,  V=25, V=25]          fp32
//   out: [N, C, V, T] fp32
//
// Factored algorithm (28 GFLOP instead of the 167.8 GFLOP fused form):
//   Stage 1: Y[w, o, j] = sum_c' W[w,o,c'] * x[n,c',w,t],  j = n*T + t
//   Stage 2: out[n,c,v,t] = sum_k sum_w A[k,w,v] * Y[w, c*3+k, j]

#define NB 32
#define CC 64
#define VV 25
#define TT 1024
#define KK 3
#define OO (KK * CC)      /* 192 */
#define NT (NB * TT)      /* 32768 */

// 629 MB scratch for the intermediate Y (device-global: allocation-free).
__device__ float g_Y[(size_t)VV * OO * NT];

// ---------------------------------------------------------------------------
// Stage 1: per-node GEMM  Y_w[192, 32768] = W_w[192,64] @ X_w[64, 32768]
// grid = (NT/128, 192/64, 25), block = 256
// CTA tile: 64 (o) x 128 (j), K=64 fully in shared memory.
// Thread micro-tile: 4 (o) x 8 (j).
// ---------------------------------------------------------------------------
__global__ __launch_bounds__(256) void stage1_kernel(
    const float* __restrict__ x, const float* __restrict__ Wg)
{
    __shared__ float Ws[64][64];    // [o_local][c']   (16 KB)
    __shared__ float Xs[64][128];   // [c'][j_local]   (32 KB)

    const int w   = blockIdx.z;
    const int o0  = blockIdx.y * 64;
    const int j0  = blockIdx.x * 128;
    const int n   = j0 >> 10;          // j0 / 1024 (tile never crosses n)
    const int t0  = j0 & 1023;
    const int tid = threadIdx.x;

    // Load W tile: 64 rows (o), 64 c' each -> 1024 float4, coalesced.
    {
        const float4* wg4 = (const float4*)(Wg + ((size_t)w * OO + o0) * 64);
        float4* ws4 = (float4*)&Ws[0][0];
        #pragma unroll
        for (int i = 0; i < 4; ++i)
            ws4[tid + i * 256] = wg4[tid + i * 256];
    }

    // Load X tile: 64 rows (c'), 128 consecutive t each -> coalesced float4.
    {
        const float* xb = x + (size_t)n * CC * VV * TT + (size_t)w * TT + t0;
        #pragma unroll
        for (int i = 0; i < 8; ++i) {
            int idx = tid + i * 256;
            int r = idx >> 5;          // c'
            int c4 = idx & 31;         // float4 index within row
            ((float4*)&Xs[r][0])[c4] =
                *(const float4*)(xb + (size_t)r * (VV * TT) + c4 * 4);
        }
    }
    __syncthreads();

    const int to = tid >> 4;   // 0..15 -> 4 consecutive o
    const int tj = tid & 15;   // 0..15 -> 8 consecutive j

    float acc[4][8];
    #pragma unroll
    for (int i = 0; i < 4; ++i)
        #pragma unroll
        for (int jv = 0; jv < 8; ++jv) acc[i][jv] = 0.0f;

    #pragma unroll 8
    for (int cc = 0; cc < 64; ++cc) {
        const float4 xa = ((const float4*)&Xs[cc][0])[tj * 2];
        const float4 xb4 = ((const float4*)&Xs[cc][0])[tj * 2 + 1];
        float wv[4];
        #pragma unroll
        for (int i = 0; i < 4; ++i) wv[i] = Ws[to * 4 + i][cc];
        #pragma unroll
        for (int i = 0; i < 4; ++i) {
            acc[i][0] += wv[i] * xa.x;
            acc[i][1] += wv[i] * xa.y;
            acc[i][2] += wv[i] * xa.z;
            acc[i][3] += wv[i] * xa.w;
            acc[i][4] += wv[i] * xb4.x;
            acc[i][5] += wv[i] * xb4.y;
            acc[i][6] += wv[i] * xb4.z;
            acc[i][7] += wv[i] * xb4.w;
        }
    }

    float* yb = g_Y + ((size_t)w * OO + o0 + to * 4) * NT + j0 + tj * 8;
    #pragma unroll
    for (int i = 0; i < 4; ++i) {
        *(float4*)(yb + (size_t)i * NT) =
            make_float4(acc[i][0], acc[i][1], acc[i][2], acc[i][3]);
        *(float4*)(yb + (size_t)i * NT + 4) =
            make_float4(acc[i][4], acc[i][5], acc[i][6], acc[i][7]);
    }
}

// ---------------------------------------------------------------------------
// Stage 2: out[n,c,v,t] = sum_{k,w} A[k,w,v] * Y[w, c*3+k, n*T+t]
// grid = (T/512, C, N), block = 128. Each thread owns ALL 25 v outputs for
// 4 consecutive t, so each Y element is loaded exactly once per thread.
// grid total = 2*64*32 = 4096 CTAs.
// ---------------------------------------------------------------------------
__global__ __launch_bounds__(128) void stage2_kernel(
    const float* __restrict__ Ag, float* __restrict__ out)
{
    __shared__ __align__(16) float As[KK * VV][28];  // rows padded to 28 for float4

    const int tid = threadIdx.x;
    for (int i = tid; i < KK * VV * VV; i += 128) {
        int r = i / VV;       // r = k*25 + w
        int v = i % VV;
        As[r][v] = Ag[i];
    }
    __syncthreads();

    const int t0 = blockIdx.x * 512 + tid * 4;
    const int c  = blockIdx.y;
    const int n  = blockIdx.z;
    const int j  = n * TT + t0;

    float acc[VV][4];
    #pragma unroll
    for (int v = 0; v < VV; ++v)
        #pragma unroll
        for (int e = 0; e < 4; ++e) acc[v][e] = 0.0f;

    for (int k = 0; k < KK; ++k) {
        #pragma unroll 1
        for (int w = 0; w < VV; ++w) {
            const float4 y4 =
                *(const float4*)(g_Y + ((size_t)w * OO + c * KK + k) * NT + j);

            // A row for (k, w): 25 values -> 6 float4 + 1 scalar from smem.
            const float4* ar4 = (const float4*)&As[k * VV + w][0];
            float a[VV];
            #pragma unroll
            for (int q = 0; q < 6; ++q) {
                float4 av = ar4[q];
                a[q * 4 + 0] = av.x; a[q * 4 + 1] = av.y;
                a[q * 4 + 2] = av.z; a[q * 4 + 3] = av.w;
            }
            a[24] = As[k * VV + w][24];

            #pragma unroll
            for (int v = 0; v < VV; ++v) {
                acc[v][0] += a[v] * y4.x;
                acc[v][1] += a[v] * y4.y;
                acc[v][2] += a[v] * y4.z;
                acc[v][3] += a[v] * y4.w;
            }
        }
    }

    float* ob = out + (((size_t)n * CC + c) * VV) * TT + t0;
    #pragma unroll
    for (int v = 0; v < VV; ++v)
        *(float4*)(ob + (size_t)v * TT) =
            make_float4(acc[v][0], acc[v][1], acc[v][2], acc[v][3]);
}

// ---------------------------------------------------------------------------
extern "C" void kernel_launch(void* const* d_in, const int* in_sizes, int n_in,
                              void* d_out, int out_size)
{
    const float* x  = (const float*)d_in[0];  // [32,64,25,1024]
    const float* Wg = (const float*)d_in[1];  // [25,192,64]
    const float* Ag = (const float*)d_in[2];  // [3,25,25]
    float* out = (float*)d_out;               // [32,64,25,1024]

    dim3 g1(NT / 128, OO / 64, VV);   // (256, 3, 25)
    stage1_kernel<<<g1, 256>>>(x, Wg);

    dim3 g2(TT / 512, CC, NB);        // (2, 64, 32)
    stage2_kernel<<<g2, 128>>>(Ag, out);
}

// round 2
// speedup vs baseline: 1.0593x; 1.0593x over previous
#include <cuda_runtime.h>
#include <cstdint>
#include <cstddef>

// Shapes: x[32,64,25,1024], W[25,192,64], A[3,25,25], out[32,64,25,1024]
// Factored algorithm (28 GFLOP):
//   Stage 1: Y[w, o, j] = sum_c' W[w,o,c'] * x[n,c',w,t],  j = n*T+t
//   Stage 2: out[n,c,v,t] = sum_k sum_w A[k,w,v] * Y[w, c*3+k, j]
// Both stages use packed fp32x2 FMAs (fma.rn.f32x2) -> 2x fp32 throughput.

#define NB 32
#define CC 64
#define VV 25
#define TT 1024
#define KK 3
#define OO (KK * CC)      /* 192 */
#define NT (NB * TT)      /* 32768 */

typedef unsigned long long u64;

// 629 MB scratch for the intermediate Y (device-global: allocation-free).
__device__ float g_Y[(size_t)VV * OO * NT];

__device__ __forceinline__ u64 pack2(float lo, float hi) {
    u64 r;
    asm("mov.b64 %0, {%1, %2};" : "=l"(r) : "f"(lo), "f"(hi));
    return r;
}
// d = a * b + d   (elementwise over 2 packed fp32 lanes)
__device__ __forceinline__ void ffma2(u64& d, u64 a, u64 b) {
    asm("fma.rn.f32x2 %0, %1, %2, %0;" : "+l"(d) : "l"(a), "l"(b));
}

// ---------------------------------------------------------------------------
// Stage 1: per-node GEMM  Y_w[192, 32768] = W_w[192,64] @ X_w[64, 32768]
// grid = (NT/128, 192/64, 25), block = 256
// CTA tile 64(o) x 128(j), K=64 resident. Thread micro-tile 4(o) x 8(j),
// accumulated as 4x4 packed f32x2 pairs.
// ---------------------------------------------------------------------------
__global__ __launch_bounds__(256) void stage1_kernel(
    const float* __restrict__ x, const float* __restrict__ Wg)
{
    __shared__ float Wt[64][68];                    // [c'][o_local], padded
    __shared__ __align__(16) float Xs[64][128];     // [c'][j_local]

    const int w   = blockIdx.z;
    const int o0  = blockIdx.y * 64;
    const int j0  = blockIdx.x * 128;
    const int n   = j0 >> 10;           // tile never crosses n
    const int t0  = j0 & 1023;
    const int tid = threadIdx.x;

    // Load W tile TRANSPOSED: Wt[c'][o]. Global reads coalesced (c' contiguous),
    // smem stores stride-68 (odd-ish pad; one-time cost).
    {
        const float* wg = Wg + ((size_t)w * OO + o0) * 64;
        #pragma unroll
        for (int i = 0; i < 16; ++i) {
            int idx = tid + i * 256;
            int cc  = idx & 63;
            int o   = idx >> 6;
            Wt[cc][o] = wg[(size_t)o * 64 + cc];
        }
    }

    // Load X tile: 64 rows (c'), 128 consecutive t each -> coalesced float4.
    {
        const float* xb = x + (size_t)n * CC * VV * TT + (size_t)w * TT + t0;
        #pragma unroll
        for (int i = 0; i < 8; ++i) {
            int idx = tid + i * 256;
            int r   = idx >> 5;
            int c4  = idx & 31;
            ((float4*)&Xs[r][0])[c4] =
                *(const float4*)(xb + (size_t)r * (VV * TT) + c4 * 4);
        }
    }
    __syncthreads();

    const int to = tid >> 4;   // 0..15 -> 4 consecutive o
    const int tj = tid & 15;   // 0..15 -> 8 consecutive j (4 f32x2 pairs)

    u64 acc[4][4];
    #pragma unroll
    for (int i = 0; i < 4; ++i)
        #pragma unroll
        for (int p = 0; p < 4; ++p) acc[i][p] = 0ull;

    #pragma unroll 8
    for (int cc = 0; cc < 64; ++cc) {
        const float4 wv = *(const float4*)&Wt[cc][to * 4];   // 1 LDS.128
        const ulonglong2 xa = *(const ulonglong2*)&Xs[cc][tj * 8];
        const ulonglong2 xb4 = *(const ulonglong2*)&Xs[cc][tj * 8 + 4];
        u64 wp0 = pack2(wv.x, wv.x);
        u64 wp1 = pack2(wv.y, wv.y);
        u64 wp2 = pack2(wv.z, wv.z);
        u64 wp3 = pack2(wv.w, wv.w);

        ffma2(acc[0][0], wp0, xa.x);  ffma2(acc[0][1], wp0, xa.y);
        ffma2(acc[0][2], wp0, xb4.x); ffma2(acc[0][3], wp0, xb4.y);
        ffma2(acc[1][0], wp1, xa.x);  ffma2(acc[1][1], wp1, xa.y);
        ffma2(acc[1][2], wp1, xb4.x); ffma2(acc[1][3], wp1, xb4.y);
        ffma2(acc[2][0], wp2, xa.x);  ffma2(acc[2][1], wp2, xa.y);
        ffma2(acc[2][2], wp2, xb4.x); ffma2(acc[2][3], wp2, xb4.y);
        ffma2(acc[3][0], wp3, xa.x);  ffma2(acc[3][1], wp3, xa.y);
        ffma2(acc[3][2], wp3, xb4.x); ffma2(acc[3][3], wp3, xb4.y);
    }

    float* yb = g_Y + ((size_t)w * OO + o0 + to * 4) * NT + j0 + tj * 8;
    #pragma unroll
    for (int i = 0; i < 4; ++i) {
        *(ulonglong2*)(yb + (size_t)i * NT)     = make_ulonglong2(acc[i][0], acc[i][1]);
        *(ulonglong2*)(yb + (size_t)i * NT + 4) = make_ulonglong2(acc[i][2], acc[i][3]);
    }
}

// ---------------------------------------------------------------------------
// Stage 2: out[n,c,v,t] = sum_{k,w} A[k,w,v] * Y[w, c*3+k, n*T+t]
// grid = (T/512, C, N), block = 128. Each thread owns all 25 v x 4 t.
// w-outer / k-inner: 3 LDG.128 issued back-to-back per w + next-w prefetch
// -> several loads in flight (fixes the measured MLP=1 starvation).
// A pre-duplicated in smem as {a,a} float2 pairs for packed FMA operands.
// ---------------------------------------------------------------------------
__global__ __launch_bounds__(128, 3) void stage2_kernel(
    const float* __restrict__ Ag, float* __restrict__ out)
{
    __shared__ __align__(16) float2 As2[KK * VV][26];   // row pad -> 16B multiple

    const int tid = threadIdx.x;
    for (int i = tid; i < KK * VV * VV; i += 128) {
        int r = i / VV;           // r = k*25 + w
        int v = i - r * VV;
        float a = Ag[i];
        As2[r][v] = make_float2(a, a);
    }
    __syncthreads();

    const int t0 = blockIdx.x * 512 + tid * 4;
    const int c  = blockIdx.y;
    const int n  = blockIdx.z;
    const int j  = n * TT + t0;

    u64 accL[VV], accH[VV];
    #pragma unroll
    for (int v = 0; v < VV; ++v) { accL[v] = 0ull; accH[v] = 0ull; }

    const float* pw = g_Y + (size_t)(c * KK) * NT + j;   // w = 0
    ulonglong2 b0 = *(const ulonglong2*)(pw);
    ulonglong2 b1 = *(const ulonglong2*)(pw + NT);
    ulonglong2 b2 = *(const ulonglong2*)(pw + 2 * NT);

    #pragma unroll 2
    for (int w = 0; w < VV; ++w) {
        // Prefetch next w's triple (clamped reload of w=24 on last iter: L2 hit).
        const float* pn = (w < VV - 1) ? (pw + (size_t)OO * NT) : pw;
        ulonglong2 n0 = *(const ulonglong2*)(pn);
        ulonglong2 n1 = *(const ulonglong2*)(pn + NT);
        ulonglong2 n2 = *(const ulonglong2*)(pn + 2 * NT);

        #pragma unroll
        for (int k = 0; k < KK; ++k) {
            u64 ylo = (k == 0) ? b0.x : ((k == 1) ? b1.x : b2.x);
            u64 yhi = (k == 0) ? b0.y : ((k == 1) ? b1.y : b2.y);
            const ulonglong2* ar = (const ulonglong2*)&As2[k * VV + w][0];
            #pragma unroll
            for (int q = 0; q < 12; ++q) {
                ulonglong2 ap = ar[q];                 // {a_v,a_v},{a_v+1,a_v+1}
                ffma2(accL[2 * q],     ap.x, ylo);
                ffma2(accH[2 * q],     ap.x, yhi);
                ffma2(accL[2 * q + 1], ap.y, ylo);
                ffma2(accH[2 * q + 1], ap.y, yhi);
            }
            u64 a24 = *(const u64*)&As2[k * VV + w][24];
            ffma2(accL[24], a24, ylo);
            ffma2(accH[24], a24, yhi);
        }
        b0 = n0; b1 = n1; b2 = n2; pw = pn;
    }

    float* ob = out + (((size_t)n * CC + c) * VV) * TT + t0;
    #pragma unroll
    for (int v = 0; v < VV; ++v)
        *(ulonglong2*)(ob + (size_t)v * TT) = make_ulonglong2(accL[v], accH[v]);
}

// ---------------------------------------------------------------------------
extern "C" void kernel_launch(void* const* d_in, const int* in_sizes, int n_in,
                              void* d_out, int out_size)
{
    const float* x  = (const float*)d_in[0];  // [32,64,25,1024]
    const float* Wg = (const float*)d_in[1];  // [25,192,64]
    const float* Ag = (const float*)d_in[2];  // [3,25,25]
    float* out = (float*)d_out;               // [32,64,25,1024]

    dim3 g1(NT / 128, OO / 64, VV);   // (256, 3, 25)
    stage1_kernel<<<g1, 256>>>(x, Wg);

    dim3 g2(TT / 512, CC, NB);        // (2, 64, 32)
    stage2_kernel<<<g2, 128>>>(Ag, out);
}

// round 4
// speedup vs baseline: 1.0996x; 1.0381x over previous
#include <cuda_runtime.h>
#include <cstdint>
#include <cstddef>

// Shapes: x[32,64,25,1024], W[25,192,64], A[3,25,25], out[32,64,25,1024]
// Factored (28 GFLOP):
//   Stage 1: Y[w, o, j] = sum_c' W[w,o,c'] * x[n,c',w,t],  j = n*T+t
//   Stage 2: out[n,c,v,t] = sum_k sum_w A[k,w,v] * Y[w, c*3+k, j]

#define NB 32
#define CC 64
#define VV 25
#define TT 1024
#define KK 3
#define OO (KK * CC)      /* 192 */
#define NT (NB * TT)      /* 32768 */

typedef unsigned long long u64;

__device__ float g_Y[(size_t)VV * OO * NT];   // 629 MB scratch

__device__ __forceinline__ void ffma2(u64& d, u64 a, u64 b) {
    asm("fma.rn.f32x2 %0, %1, %2, %0;" : "+l"(d) : "l"(a), "l"(b));
}

// ---------------------------------------------------------------------------
// Stage 1: per-node GEMM Y_w[192,32768] = W_w[192,64] @ X_w[64,32768]
// grid = (384, 25): o-tile fastest (3 per j-tile) so x tile hits L2.
// CTA tile 64(o) x 256(j); thread (to=tid>>5, tj=tid&31) owns 8o x 8j.
// W kept in smem pre-duplicated {w,w} -> packed FFMA2 operands via LDS only.
// smem: Wd 32KB + Xs 64KB = 96KB dynamic -> 2 CTA/SM.
// ---------------------------------------------------------------------------
__global__ __launch_bounds__(256) void stage1_kernel(
    const float* __restrict__ x, const float* __restrict__ Wg)
{
    extern __shared__ float smem[];
    float2* Wd = (float2*)smem;            // [c'][o] as {w,w}, 64*64 float2
    float*  Xs = smem + 2 * 64 * 64;       // [c'][j], 64*256 floats

    const int bx = blockIdx.x;
    const int o0 = (bx % 3) * 64;
    const int j0 = (bx / 3) * 256;         // never crosses n (1024 % 256 == 0)
    const int w  = blockIdx.y;
    const int n  = j0 >> 10;
    const int t0 = j0 & 1023;
    const int tid = threadIdx.x;

    // Fill Wd[c'][o] = {W[w,o0+o,c'], same}. Global reads coalesced in c'.
    {
        const float* wg = Wg + ((size_t)w * OO + o0) * 64;
        #pragma unroll
        for (int i = 0; i < 16; ++i) {
            int idx = tid + i * 256;       // 0..4095
            int o   = idx >> 6;
            int cc  = idx & 63;
            float v = wg[(size_t)o * 64 + cc];
            Wd[cc * 64 + o] = make_float2(v, v);
        }
    }
    // Fill Xs[c'][0..255] from x[n, c', w, t0..t0+255], coalesced float4.
    {
        const float* xb = x + (size_t)n * CC * VV * TT + (size_t)w * TT + t0;
        #pragma unroll
        for (int i = 0; i < 16; ++i) {
            int idx = tid + i * 256;       // 0..4095 float4 slots
            int r   = idx >> 6;            // c'
            int c4  = idx & 63;
            ((float4*)Xs)[r * 64 + c4] =
                *(const float4*)(xb + (size_t)r * (VV * TT) + c4 * 4);
        }
    }
    __syncthreads();

    const int to = tid >> 5;   // 0..7  -> 8 consecutive o
    const int tj = tid & 31;   // 0..31 -> 8 consecutive j (4 f32x2 pairs)

    u64 acc[8][4];
    #pragma unroll
    for (int i = 0; i < 8; ++i)
        #pragma unroll
        for (int p = 0; p < 4; ++p) acc[i][p] = 0ull;

    // Row strides in ulonglong2 units:
    //   Wd row = 64 float2 = 512 B = 32 ulonglong2
    //   Xs row = 256 float = 1024 B = 64 ulonglong2   (R3 bug: used 32 here)
    const ulonglong2* wbase = (const ulonglong2*)(Wd + to * 8);
    const ulonglong2* xbase = (const ulonglong2*)(Xs + tj * 8);

    #pragma unroll 8
    for (int cc = 0; cc < 64; ++cc) {
        // 8 duplicated w-pairs: 4 broadcast LDS.128
        ulonglong2 w01 = wbase[cc * 32 + 0];
        ulonglong2 w23 = wbase[cc * 32 + 1];
        ulonglong2 w45 = wbase[cc * 32 + 2];
        ulonglong2 w67 = wbase[cc * 32 + 3];
        // 8 x values: 2 LDS.128
        ulonglong2 xa  = xbase[cc * 64 + 0];
        ulonglong2 xb2 = xbase[cc * 64 + 1];

        ffma2(acc[0][0], w01.x, xa.x);  ffma2(acc[0][1], w01.x, xa.y);
        ffma2(acc[0][2], w01.x, xb2.x); ffma2(acc[0][3], w01.x, xb2.y);
        ffma2(acc[1][0], w01.y, xa.x);  ffma2(acc[1][1], w01.y, xa.y);
        ffma2(acc[1][2], w01.y, xb2.x); ffma2(acc[1][3], w01.y, xb2.y);
        ffma2(acc[2][0], w23.x, xa.x);  ffma2(acc[2][1], w23.x, xa.y);
        ffma2(acc[2][2], w23.x, xb2.x); ffma2(acc[2][3], w23.x, xb2.y);
        ffma2(acc[3][0], w23.y, xa.x);  ffma2(acc[3][1], w23.y, xa.y);
        ffma2(acc[3][2], w23.y, xb2.x); ffma2(acc[3][3], w23.y, xb2.y);
        ffma2(acc[4][0], w45.x, xa.x);  ffma2(acc[4][1], w45.x, xa.y);
        ffma2(acc[4][2], w45.x, xb2.x); ffma2(acc[4][3], w45.x, xb2.y);
        ffma2(acc[5][0], w45.y, xa.x);  ffma2(acc[5][1], w45.y, xa.y);
        ffma2(acc[5][2], w45.y, xb2.x); ffma2(acc[5][3], w45.y, xb2.y);
        ffma2(acc[6][0], w67.x, xa.x);  ffma2(acc[6][1], w67.x, xa.y);
        ffma2(acc[6][2], w67.x, xb2.x); ffma2(acc[6][3], w67.x, xb2.y);
        ffma2(acc[7][0], w67.y, xa.x);  ffma2(acc[7][1], w67.y, xa.y);
        ffma2(acc[7][2], w67.y, xb2.x); ffma2(acc[7][3], w67.y, xb2.y);
    }

    float* yb = g_Y + ((size_t)w * OO + o0 + to * 8) * NT + j0 + tj * 8;
    #pragma unroll
    for (int i = 0; i < 8; ++i) {
        *(ulonglong2*)(yb + (size_t)i * NT)     = make_ulonglong2(acc[i][0], acc[i][1]);
        *(ulonglong2*)(yb + (size_t)i * NT + 4) = make_ulonglong2(acc[i][2], acc[i][3]);
    }
}

// ---------------------------------------------------------------------------
// Stage 2: out[n,c,v,t] = sum_{k,w} A[k,w,v] * Y[w, c*3+k, n*T+t]
// grid = (T/512, C, N), block = 128; thread owns 25v x 4t.
// Straight-line w loop (0..23 prefetch next, epilogue w=24) -> no selects.
// ---------------------------------------------------------------------------
__global__ __launch_bounds__(128, 3) void stage2_kernel(
    const float* __restrict__ Ag, float* __restrict__ out)
{
    __shared__ __align__(16) float2 As2[KK * VV][26];

    const int tid = threadIdx.x;
    for (int i = tid; i < KK * VV * VV; i += 128) {
        int r = i / VV;
        int v = i - r * VV;
        float a = Ag[i];
        As2[r][v] = make_float2(a, a);
    }
    __syncthreads();

    const int t0 = blockIdx.x * 512 + tid * 4;
    const int c  = blockIdx.y;
    const int n  = blockIdx.z;
    const int j  = n * TT + t0;

    u64 accL[VV], accH[VV];
    #pragma unroll
    for (int v = 0; v < VV; ++v) { accL[v] = 0ull; accH[v] = 0ull; }

    const float* pw = g_Y + (size_t)(c * KK) * NT + j;    // w = 0
    ulonglong2 b[3];
    b[0] = *(const ulonglong2*)(pw);
    b[1] = *(const ulonglong2*)(pw + NT);
    b[2] = *(const ulonglong2*)(pw + 2 * NT);

    #pragma unroll 2
    for (int w = 0; w < VV - 1; ++w) {
        const float* pn = pw + (size_t)OO * NT;
        ulonglong2 nb0 = *(const ulonglong2*)(pn);
        ulonglong2 nb1 = *(const ulonglong2*)(pn + NT);
        ulonglong2 nb2 = *(const ulonglong2*)(pn + 2 * NT);

        #pragma unroll
        for (int k = 0; k < KK; ++k) {
            u64 ylo = b[k].x, yhi = b[k].y;
            const ulonglong2* ar = (const ulonglong2*)&As2[k * VV + w][0];
            #pragma unroll
            for (int q = 0; q < 12; ++q) {
                ulonglong2 ap = ar[q];
                ffma2(accL[2 * q],     ap.x, ylo);
                ffma2(accH[2 * q],     ap.x, yhi);
                ffma2(accL[2 * q + 1], ap.y, ylo);
                ffma2(accH[2 * q + 1], ap.y, yhi);
            }
            u64 a24 = *(const u64*)&As2[k * VV + w][24];
            ffma2(accL[24], a24, ylo);
            ffma2(accH[24], a24, yhi);
        }
        b[0] = nb0; b[1] = nb1; b[2] = nb2; pw = pn;
    }
    // w = 24 epilogue
    #pragma unroll
    for (int k = 0; k < KK; ++k) {
        u64 ylo = b[k].x, yhi = b[k].y;
        const ulonglong2* ar = (const ulonglong2*)&As2[k * VV + (VV - 1)][0];
        #pragma unroll
        for (int q = 0; q < 12; ++q) {
            ulonglong2 ap = ar[q];
            ffma2(accL[2 * q],     ap.x, ylo);
            ffma2(accH[2 * q],     ap.x, yhi);
            ffma2(accL[2 * q + 1], ap.y, ylo);
            ffma2(accH[2 * q + 1], ap.y, yhi);
        }
        u64 a24 = *(const u64*)&As2[k * VV + (VV - 1)][24];
        ffma2(accL[24], a24, ylo);
        ffma2(accH[24], a24, yhi);
    }

    float* ob = out + (((size_t)n * CC + c) * VV) * TT + t0;
    #pragma unroll
    for (int v = 0; v < VV; ++v)
        *(ulonglong2*)(ob + (size_t)v * TT) = make_ulonglong2(accL[v], accH[v]);
}

// ---------------------------------------------------------------------------
extern "C" void kernel_launch(void* const* d_in, const int* in_sizes, int n_in,
                              void* d_out, int out_size)
{
    const float* x  = (const float*)d_in[0];
    const float* Wg = (const float*)d_in[1];
    const float* Ag = (const float*)d_in[2];
    float* out = (float*)d_out;

    cudaFuncSetAttribute(stage1_kernel,
                         cudaFuncAttributeMaxDynamicSharedMemorySize,
                         96 * 1024);

    dim3 g1(384, 25);                 // o fastest -> x tile L2 reuse
    stage1_kernel<<<g1, 256, 96 * 1024>>>(x, Wg);

    dim3 g2(TT / 512, CC, NB);        // (2, 64, 32)
    stage2_kernel<<<g2, 128>>>(Ag, out);
}

// round 6
// speedup vs baseline: 1.9802x; 1.8008x over previous
#include <cuda_runtime.h>
#include <cuda_fp16.h>
#include <cuda_bf16.h>
#include <cstdint>
#include <cstddef>

// Shapes: x[32,64,25,1024], W[25,192,64], A[3,25,25], out[32,64,25,1024]
// Stage 1 (HMMA bf16-split): Y[(k*1600 + w*64 + c)][j] (fp16)
//                            = sum_c' W[w, c*3+k, c'] * x[n, c', w, t],  j=n*T+t
// Stage 2 (FFMA2):           out[n,c,v,t] = sum_k sum_w A[k,w,v] * Y[...][j]

#define NB 32
#define CC 64
#define VV 25
#define TT 1024
#define KK 3
#define OO (KK * CC)      /* 192 */
#define NT (NB * TT)      /* 32768 */
#define WSTRIDE 72        /* padded row stride (bf16/half units) */

typedef unsigned long long u64;

// 315 MB fp16 scratch for Y (device-global: allocation-free).
__device__ unsigned short g_Yh[(size_t)VV * OO * NT];

// ---------------------------------------------------------------------------
// helpers
// ---------------------------------------------------------------------------
__device__ __forceinline__ void ffma2(u64& d, u64 a, u64 b) {
    asm("fma.rn.f32x2 %0, %1, %2, %0;" : "+l"(d) : "l"(a), "l"(b));
}
__device__ __forceinline__ u64 pack2(float lo, float hi) {
    u64 r; asm("mov.b64 %0, {%1, %2};" : "=l"(r) : "f"(lo), "f"(hi)); return r;
}
__device__ __forceinline__ uint32_t smem_u32(const void* p) {
    uint32_t a;
    asm("{ .reg .u64 t; cvta.to.shared.u64 t, %1; cvt.u32.u64 %0, t; }"
        : "=r"(a) : "l"(p));
    return a;
}
// pack (a, b) -> bf16x2 with a in the LOW half (lower address)
__device__ __forceinline__ uint32_t bf16x2_of(float a, float b) {
    uint32_t r;
    asm("cvt.rn.satfinite.bf16x2.f32 %0, %1, %2;" : "=r"(r) : "f"(b), "f"(a));
    return r;
}
__device__ __forceinline__ void ldm_x4(uint32_t a[4], uint32_t addr) {
    asm volatile("ldmatrix.sync.aligned.m8n8.x4.shared.b16 {%0,%1,%2,%3}, [%4];"
        : "=r"(a[0]), "=r"(a[1]), "=r"(a[2]), "=r"(a[3]) : "r"(addr));
}
__device__ __forceinline__ void ldm_x2t(uint32_t b[2], uint32_t addr) {
    asm volatile("ldmatrix.sync.aligned.m8n8.x2.trans.shared.b16 {%0,%1}, [%2];"
        : "=r"(b[0]), "=r"(b[1]) : "r"(addr));
}
__device__ __forceinline__ void mma16816(float c[4], const uint32_t a[4],
                                         const uint32_t b[2]) {
    asm volatile("mma.sync.aligned.m16n8k16.row.col.f32.bf16.bf16.f32 "
        "{%0,%1,%2,%3}, {%4,%5,%6,%7}, {%8,%9}, {%0,%1,%2,%3};"
        : "+f"(c[0]), "+f"(c[1]), "+f"(c[2]), "+f"(c[3])
        : "r"(a[0]), "r"(a[1]), "r"(a[2]), "r"(a[3]), "r"(b[0]), "r"(b[1]));
}

// ---------------------------------------------------------------------------
// Stage 1: per (w, 64-j tile): D[192, 64] = W_w[192,64] @ X_w[64,64]
// bf16 hi/lo split, 3 passes (hh + lh + hl), fp32 accum, fp16 Y out.
// smem (73728 B): Wh@0 (192x72 bf16), Wl@27648, Xh@55296 (64x72), Xl@64512.
// Epilogue stages D in the Wh region for coalesced 128B/row Y writes.
// ---------------------------------------------------------------------------
__global__ __launch_bounds__(256, 2) void stage1_mma(
    const float* __restrict__ x, const float* __restrict__ Wg)
{
    extern __shared__ char smem[];
    const uint32_t sb = smem_u32(smem);
    const uint32_t WH = sb;
    const uint32_t WL = sb + 27648;
    const uint32_t XH = sb + 55296;
    const uint32_t XL = sb + 64512;

    const int tid = threadIdx.x;
    const int w   = blockIdx.y;
    const int j0  = blockIdx.x * 64;
    const int n   = j0 >> 10;          // tile never crosses n (1024 % 64 == 0)
    const int t0  = j0 & 1023;

    // ---- W[w] 192x64 fp32 -> Wh/Wl bf16, padded rows ----
    {
        const float* wg = Wg + (size_t)w * OO * 64;
        #pragma unroll
        for (int i = 0; i < 24; ++i) {
            int idx = tid + i * 256;        // float2 index, 0..6143
            int o   = idx >> 5;
            int cp  = idx & 31;
            float2 wv = *(const float2*)(wg + (size_t)o * 64 + cp * 2);
            uint32_t hp = bf16x2_of(wv.x, wv.y);
            float h0 = __uint_as_float(hp << 16);
            float h1 = __uint_as_float(hp & 0xFFFF0000u);
            uint32_t lp = bf16x2_of(wv.x - h0, wv.y - h1);
            int boff = (o * WSTRIDE + cp * 2) * 2;
            *(uint32_t*)(smem + boff)         = hp;
            *(uint32_t*)(smem + 27648 + boff) = lp;
        }
    }
    // ---- X tile 64(c') x 64(j) fp32 -> Xh/Xl bf16 ----
    {
        const float* xb = x + (size_t)n * CC * VV * TT + (size_t)w * TT + t0;
        #pragma unroll
        for (int i = 0; i < 8; ++i) {
            int idx = tid + i * 256;        // float2 index, 0..2047
            int r   = idx >> 5;             // c'
            int cp  = idx & 31;
            float2 xv = *(const float2*)(xb + (size_t)r * (VV * TT) + cp * 2);
            uint32_t hp = bf16x2_of(xv.x, xv.y);
            float h0 = __uint_as_float(hp << 16);
            float h1 = __uint_as_float(hp & 0xFFFF0000u);
            uint32_t lp = bf16x2_of(xv.x - h0, xv.y - h1);
            int boff = (r * WSTRIDE + cp * 2) * 2;
            *(uint32_t*)(smem + 55296 + boff) = hp;
            *(uint32_t*)(smem + 64512 + boff) = lp;
        }
    }
    __syncthreads();

    const int wid = tid >> 5, lane = tid & 31;
    const int mg = wid >> 1, jg = wid & 1;
    const int m0 = mg * 48, n0 = jg * 32;

    // ldmatrix per-lane row/col offsets
    const int arow  = lane & 15;            // A: lanes 0-15 rows, 16-31 rows (k+8)
    const int acolb = (lane >> 4) * 8;
    const int brow  = lane & 15;            // B (.x2): lanes 0-15 supply k-rows

    float acc[3][4][4] = {};

    #pragma unroll
    for (int ks = 0; ks < 4; ++ks) {
        uint32_t Ah[3][4], Al[3][4], Bh[4][2], Bl[4][2];
        #pragma unroll
        for (int i = 0; i < 3; ++i) {
            uint32_t off = (uint32_t)(((m0 + 16 * i + arow) * WSTRIDE
                                       + ks * 16 + acolb) * 2);
            ldm_x4(Ah[i], WH + off);
            ldm_x4(Al[i], WL + off);
        }
        #pragma unroll
        for (int t = 0; t < 4; ++t) {
            uint32_t off = (uint32_t)(((ks * 16 + brow) * WSTRIDE
                                       + n0 + 8 * t) * 2);
            ldm_x2t(Bh[t], XH + off);
            ldm_x2t(Bl[t], XL + off);
        }
        #pragma unroll
        for (int i = 0; i < 3; ++i)
            #pragma unroll
            for (int t = 0; t < 4; ++t) {
                mma16816(acc[i][t], Ah[i], Bh[t]);   // hi*hi
                mma16816(acc[i][t], Al[i], Bh[t]);   // lo*hi
                mma16816(acc[i][t], Ah[i], Bl[t]);   // hi*lo
            }
    }
    __syncthreads();   // all ldmatrix reads done before staging overwrites Wh

    // ---- stage D[o, jloc] as fp16 in smem (Wh region, stride WSTRIDE) ----
    {
        const int r = lane >> 2, q = lane & 3;
        #pragma unroll
        for (int i = 0; i < 3; ++i)
            #pragma unroll
            for (int t = 0; t < 4; ++t) {
                int row = m0 + 16 * i + r;
                int col = n0 + 8 * t + 2 * q;
                *(half2*)(smem + (row * WSTRIDE + col) * 2) =
                    __floats2half2_rn(acc[i][t][0], acc[i][t][1]);
                *(half2*)(smem + ((row + 8) * WSTRIDE + col) * 2) =
                    __floats2half2_rn(acc[i][t][2], acc[i][t][3]);
            }
    }
    __syncthreads();

    // ---- copy out: 192 rows x 64 half (128 B contiguous per row) ----
    #pragma unroll
    for (int i = 0; i < 24; ++i) {
        int idx = tid + i * 256;          // 0..6143
        int row = idx >> 5;               // o
        int u   = idx & 31;               // u32 slot (2 halves)
        uint32_t val = *(uint32_t*)(smem + row * (WSTRIDE * 2) + u * 4);
        int cch = row / 3;
        int kk  = row - 3 * cch;
        size_t yrow = (size_t)(kk * (VV * CC) + w * CC + cch);
        *(uint32_t*)((char*)g_Yh + (yrow * NT + j0) * 2 + u * 4) = val;
    }
}

// ---------------------------------------------------------------------------
// Stage 2: out[n,c,v,t] = sum_{k,w} A[k,w,v] * Yh[(k*1600 + w*64 + c)][j]
// grid = (T/512, C, N), block = 128; thread owns 25v x 4t. fp16 Y loads (8B),
// converted to packed f32x2. Prefetch next w's 3 loads.
// ---------------------------------------------------------------------------
__device__ __forceinline__ void h4_cvt(u64 h4, u64& lo, u64& hi) {
    __half2 a = *reinterpret_cast<__half2*>(&h4);
    __half2 b = *(reinterpret_cast<__half2*>(&h4) + 1);
    float2 fa = __half22float2(a);
    float2 fb = __half22float2(b);
    lo = pack2(fa.x, fa.y);
    hi = pack2(fb.x, fb.y);
}

__global__ __launch_bounds__(128, 3) void stage2_kernel(
    const float* __restrict__ Ag, float* __restrict__ out)
{
    __shared__ __align__(16) float2 As2[KK * VV][26];

    const int tid = threadIdx.x;
    for (int i = tid; i < KK * VV * VV; i += 128) {
        int r = i / VV;
        int v = i - r * VV;
        float a = Ag[i];
        As2[r][v] = make_float2(a, a);
    }
    __syncthreads();

    const int t0 = blockIdx.x * 512 + tid * 4;
    const int c  = blockIdx.y;
    const int n  = blockIdx.z;
    const int j  = n * TT + t0;

    u64 accL[VV], accH[VV];
    #pragma unroll
    for (int v = 0; v < VV; ++v) { accL[v] = 0ull; accH[v] = 0ull; }

    const size_t KSTR = (size_t)(VV * CC) * NT;   // k stride
    const size_t WSTR = (size_t)CC * NT;          // w stride
    const unsigned short* p = g_Yh + (size_t)c * NT + j;

    u64 b0 = *(const u64*)(p);
    u64 b1 = *(const u64*)(p + KSTR);
    u64 b2 = *(const u64*)(p + 2 * KSTR);

    #pragma unroll 2
    for (int w = 0; w < VV - 1; ++w) {
        const unsigned short* pn = p + WSTR;
        u64 nb0 = *(const u64*)(pn);
        u64 nb1 = *(const u64*)(pn + KSTR);
        u64 nb2 = *(const u64*)(pn + 2 * KSTR);

        u64 yv[3][2];
        h4_cvt(b0, yv[0][0], yv[0][1]);
        h4_cvt(b1, yv[1][0], yv[1][1]);
        h4_cvt(b2, yv[2][0], yv[2][1]);

        #pragma unroll
        for (int k = 0; k < KK; ++k) {
            u64 ylo = yv[k][0], yhi = yv[k][1];
            const ulonglong2* ar = (const ulonglong2*)&As2[k * VV + w][0];
            #pragma unroll
            for (int q = 0; q < 12; ++q) {
                ulonglong2 ap = ar[q];
                ffma2(accL[2 * q],     ap.x, ylo);
                ffma2(accH[2 * q],     ap.x, yhi);
                ffma2(accL[2 * q + 1], ap.y, ylo);
                ffma2(accH[2 * q + 1], ap.y, yhi);
            }
            u64 a24 = *(const u64*)&As2[k * VV + w][24];
            ffma2(accL[24], a24, ylo);
            ffma2(accH[24], a24, yhi);
        }
        b0 = nb0; b1 = nb1; b2 = nb2; p = pn;
    }
    {   // w = 24 epilogue
        u64 yv[3][2];
        h4_cvt(b0, yv[0][0], yv[0][1]);
        h4_cvt(b1, yv[1][0], yv[1][1]);
        h4_cvt(b2, yv[2][0], yv[2][1]);
        #pragma unroll
        for (int k = 0; k < KK; ++k) {
            u64 ylo = yv[k][0], yhi = yv[k][1];
            const ulonglong2* ar = (const ulonglong2*)&As2[k * VV + (VV - 1)][0];
            #pragma unroll
            for (int q = 0; q < 12; ++q) {
                ulonglong2 ap = ar[q];
                ffma2(accL[2 * q],     ap.x, ylo);
                ffma2(accH[2 * q],     ap.x, yhi);
                ffma2(accL[2 * q + 1], ap.y, ylo);
                ffma2(accH[2 * q + 1], ap.y, yhi);
            }
            u64 a24 = *(const u64*)&As2[k * VV + (VV - 1)][24];
            ffma2(accL[24], a24, ylo);
            ffma2(accH[24], a24, yhi);
        }
    }

    float* ob = out + (((size_t)n * CC + c) * VV) * TT + t0;
    #pragma unroll
    for (int v = 0; v < VV; ++v)
        *(ulonglong2*)(ob + (size_t)v * TT) = make_ulonglong2(accL[v], accH[v]);
}

// ---------------------------------------------------------------------------
extern "C" void kernel_launch(void* const* d_in, const int* in_sizes, int n_in,
                              void* d_out, int out_size)
{
    const float* x  = (const float*)d_in[0];
    const float* Wg = (const float*)d_in[1];
    const float* Ag = (const float*)d_in[2];
    float* out = (float*)d_out;

    cudaFuncSetAttribute(stage1_mma,
                         cudaFuncAttributeMaxDynamicSharedMemorySize,
                         73728);

    dim3 g1(NT / 64, VV);             // (512, 25)
    stage1_mma<<<g1, 256, 73728>>>(x, Wg);

    dim3 g2(TT / 512, CC, NB);        // (2, 64, 32)
    stage2_kernel<<<g2, 128>>>(Ag, out);
}

// round 7
// speedup vs baseline: 2.8959x; 1.4624x over previous
#include <cuda_runtime.h>
#include <cuda_fp16.h>
#include <cuda_bf16.h>
#include <cstdint>
#include <cstddef>

// Shapes: x[32,64,25,1024], W[25,192,64], A[3,25,25], out[32,64,25,1024]
// Stage 1 (HMMA bf16-split): Yh[c*75 + k*25 + w][j] (fp16)
//                            = sum_c' W[w, c*3+k, c'] * x[n, c', w, t], j=n*T+t
// Stage 2 (HMMA fp16, A hi/lo split):
//   out[n,c,v,t] = sum_r Agraph[v,r] * Yh[c*75 + r][j],  r = k*25+w

#define NB 32
#define CC 64
#define VV 25
#define TT 1024
#define KK 3
#define OO (KK * CC)      /* 192 */
#define NT (NB * TT)      /* 32768 */
#define WSTRIDE 72        /* stage1 padded row stride (bf16/half units) */

typedef unsigned long long u64;

// 315 MB fp16 scratch for Y (device-global: allocation-free).
__device__ unsigned short g_Yh[(size_t)VV * OO * NT];

// ---------------------------------------------------------------------------
// helpers
// ---------------------------------------------------------------------------
__device__ __forceinline__ uint32_t smem_u32(const void* p) {
    uint32_t a;
    asm("{ .reg .u64 t; cvta.to.shared.u64 t, %1; cvt.u32.u64 %0, t; }"
        : "=r"(a) : "l"(p));
    return a;
}
// pack (a, b) -> bf16x2 with a in the LOW half
__device__ __forceinline__ uint32_t bf16x2_of(float a, float b) {
    uint32_t r;
    asm("cvt.rn.satfinite.bf16x2.f32 %0, %1, %2;" : "=r"(r) : "f"(b), "f"(a));
    return r;
}
__device__ __forceinline__ void ldm_x4(uint32_t a[4], uint32_t addr) {
    asm volatile("ldmatrix.sync.aligned.m8n8.x4.shared.b16 {%0,%1,%2,%3}, [%4];"
        : "=r"(a[0]), "=r"(a[1]), "=r"(a[2]), "=r"(a[3]) : "r"(addr));
}
__device__ __forceinline__ void ldm_x2t(uint32_t b[2], uint32_t addr) {
    asm volatile("ldmatrix.sync.aligned.m8n8.x2.trans.shared.b16 {%0,%1}, [%2];"
        : "=r"(b[0]), "=r"(b[1]) : "r"(addr));
}
__device__ __forceinline__ void mma_bf16(float c[4], const uint32_t a[4],
                                         const uint32_t b[2]) {
    asm volatile("mma.sync.aligned.m16n8k16.row.col.f32.bf16.bf16.f32 "
        "{%0,%1,%2,%3}, {%4,%5,%6,%7}, {%8,%9}, {%0,%1,%2,%3};"
        : "+f"(c[0]), "+f"(c[1]), "+f"(c[2]), "+f"(c[3])
        : "r"(a[0]), "r"(a[1]), "r"(a[2]), "r"(a[3]), "r"(b[0]), "r"(b[1]));
}
__device__ __forceinline__ void mma_f16(float c[4], const uint32_t a[4],
                                        const uint32_t b[2]) {
    asm volatile("mma.sync.aligned.m16n8k16.row.col.f32.f16.f16.f32 "
        "{%0,%1,%2,%3}, {%4,%5,%6,%7}, {%8,%9}, {%0,%1,%2,%3};"
        : "+f"(c[0]), "+f"(c[1]), "+f"(c[2]), "+f"(c[3])
        : "r"(a[0]), "r"(a[1]), "r"(a[2]), "r"(a[3]), "r"(b[0]), "r"(b[1]));
}

// ---------------------------------------------------------------------------
// Stage 1: per (w, 64-j tile): D[192, 64] = W_w[192,64] @ X_w[64,64]
// bf16 hi/lo split, 3 passes (hh + lh + hl), fp32 accum, fp16 Y out.
// smem (73728 B): Wh@0 (192x72 bf16), Wl@27648, Xh@55296 (64x72), Xl@64512.
// ---------------------------------------------------------------------------
__global__ __launch_bounds__(256, 2) void stage1_mma(
    const float* __restrict__ x, const float* __restrict__ Wg)
{
    extern __shared__ char smem[];
    const uint32_t sb = smem_u32(smem);
    const uint32_t WH = sb;
    const uint32_t WL = sb + 27648;
    const uint32_t XH = sb + 55296;
    const uint32_t XL = sb + 64512;

    const int tid = threadIdx.x;
    const int w   = blockIdx.y;
    const int j0  = blockIdx.x * 64;
    const int n   = j0 >> 10;
    const int t0  = j0 & 1023;

    // W[w] 192x64 fp32 -> Wh/Wl bf16
    {
        const float* wg = Wg + (size_t)w * OO * 64;
        #pragma unroll
        for (int i = 0; i < 24; ++i) {
            int idx = tid + i * 256;
            int o   = idx >> 5;
            int cp  = idx & 31;
            float2 wv = *(const float2*)(wg + (size_t)o * 64 + cp * 2);
            uint32_t hp = bf16x2_of(wv.x, wv.y);
            float h0 = __uint_as_float(hp << 16);
            float h1 = __uint_as_float(hp & 0xFFFF0000u);
            uint32_t lp = bf16x2_of(wv.x - h0, wv.y - h1);
            int boff = (o * WSTRIDE + cp * 2) * 2;
            *(uint32_t*)(smem + boff)         = hp;
            *(uint32_t*)(smem + 27648 + boff) = lp;
        }
    }
    // X tile 64(c') x 64(j) -> Xh/Xl bf16
    {
        const float* xb = x + (size_t)n * CC * VV * TT + (size_t)w * TT + t0;
        #pragma unroll
        for (int i = 0; i < 8; ++i) {
            int idx = tid + i * 256;
            int r   = idx >> 5;
            int cp  = idx & 31;
            float2 xv = *(const float2*)(xb + (size_t)r * (VV * TT) + cp * 2);
            uint32_t hp = bf16x2_of(xv.x, xv.y);
            float h0 = __uint_as_float(hp << 16);
            float h1 = __uint_as_float(hp & 0xFFFF0000u);
            uint32_t lp = bf16x2_of(xv.x - h0, xv.y - h1);
            int boff = (r * WSTRIDE + cp * 2) * 2;
            *(uint32_t*)(smem + 55296 + boff) = hp;
            *(uint32_t*)(smem + 64512 + boff) = lp;
        }
    }
    __syncthreads();

    const int wid = tid >> 5, lane = tid & 31;
    const int mg = wid >> 1, jg = wid & 1;
    const int m0 = mg * 48, n0 = jg * 32;

    const int arow  = lane & 15;
    const int acolb = (lane >> 4) * 8;
    const int brow  = lane & 15;

    float acc[3][4][4] = {};

    #pragma unroll
    for (int ks = 0; ks < 4; ++ks) {
        uint32_t Ah[3][4], Al[3][4], Bh[4][2], Bl[4][2];
        #pragma unroll
        for (int i = 0; i < 3; ++i) {
            uint32_t off = (uint32_t)(((m0 + 16 * i + arow) * WSTRIDE
                                       + ks * 16 + acolb) * 2);
            ldm_x4(Ah[i], WH + off);
            ldm_x4(Al[i], WL + off);
        }
        #pragma unroll
        for (int t = 0; t < 4; ++t) {
            uint32_t off = (uint32_t)(((ks * 16 + brow) * WSTRIDE
                                       + n0 + 8 * t) * 2);
            ldm_x2t(Bh[t], XH + off);
            ldm_x2t(Bl[t], XL + off);
        }
        #pragma unroll
        for (int i = 0; i < 3; ++i)
            #pragma unroll
            for (int t = 0; t < 4; ++t) {
                mma_bf16(acc[i][t], Ah[i], Bh[t]);
                mma_bf16(acc[i][t], Al[i], Bh[t]);
                mma_bf16(acc[i][t], Ah[i], Bl[t]);
            }
    }
    __syncthreads();

    // stage D[o, jloc] as fp16 in smem (Wh region)
    {
        const int r = lane >> 2, q = lane & 3;
        #pragma unroll
        for (int i = 0; i < 3; ++i)
            #pragma unroll
            for (int t = 0; t < 4; ++t) {
                int row = m0 + 16 * i + r;
                int col = n0 + 8 * t + 2 * q;
                *(half2*)(smem + (row * WSTRIDE + col) * 2) =
                    __floats2half2_rn(acc[i][t][0], acc[i][t][1]);
                *(half2*)(smem + ((row + 8) * WSTRIDE + col) * 2) =
                    __floats2half2_rn(acc[i][t][2], acc[i][t][3]);
            }
    }
    __syncthreads();

    // copy out: Y row = c*75 + k*25 + w  (c = o/3, k = o%3)
    #pragma unroll
    for (int i = 0; i < 24; ++i) {
        int idx = tid + i * 256;
        int row = idx >> 5;               // o
        int u   = idx & 31;
        uint32_t val = *(uint32_t*)(smem + row * (WSTRIDE * 2) + u * 4);
        int cch = row / 3;
        int kk  = row - 3 * cch;
        size_t yrow = (size_t)(cch * 75 + kk * VV + w);
        *(uint32_t*)((char*)g_Yh + (yrow * NT + j0) * 2 + u * 4) = val;
    }
}

// ---------------------------------------------------------------------------
// Stage 2 (HMMA): out[v, (c,j)] = sum_r Agraph[v,r] * Yh[c*75+r][j]
// A-op = graph matrix [v:25->32, r:75->80] fp16 hi/lo (2 passes).
// B-op = Y slice [r rows][128 j cols], ldmatrix.x2.trans.
// grid = (NT/128 j-tiles, 8 c-groups); CTA loops 8 c values.
// Per warp: D[v=32 (2 m-tiles), j=16 (2 n-tiles)]; 8 warps cover 128 j.
// ---------------------------------------------------------------------------
#define JT  128
#define AST 88     /* graph A smem stride (halves): 176B/16=11 odd -> no conflicts */
#define YST 136    /* Y slice smem stride (halves): 272B/16=17 odd -> no conflicts */

__global__ __launch_bounds__(256) void stage2_mma(
    const float* __restrict__ Ag, float* __restrict__ out)
{
    __shared__ __align__(16) __half sAh[32 * AST];
    __shared__ __align__(16) __half sAl[32 * AST];
    __shared__ __align__(16) __half sY[80 * YST];

    const uint32_t AH = smem_u32(sAh);
    const uint32_t AL = smem_u32(sAl);
    const uint32_t YS = smem_u32(sY);

    const int tid = threadIdx.x;
    const int j0  = blockIdx.x * JT;
    const int c0  = blockIdx.y * 8;
    const int n   = j0 >> 10;            // JT=128 tile never crosses n
    const int tt0 = j0 & 1023;

    // Build graph-A hi/lo fp16: sA[v][r], zero-padded (v>=25 or r>=75).
    for (int i = tid; i < 80 * 32; i += 256) {
        int r = i >> 5;
        int v = i & 31;
        float a = (r < 75 && v < 25) ? Ag[r * 25 + v] : 0.0f;
        __half h = __float2half_rn(a);
        __half l = __float2half_rn(a - __half2float(h));
        sAh[v * AST + r] = h;
        sAl[v * AST + r] = l;
    }

    const int wid  = tid >> 5, lane = tid & 31;
    const int jw   = wid * 16;           // warp's j offset inside tile
    const int arow = lane & 15, acolb = (lane >> 4) * 8;
    const int brow = lane & 15;
    const int r4   = lane >> 2, q2 = (lane & 3) * 2;

    for (int ci = 0; ci < 8; ++ci) {
        const int c = c0 + ci;
        __syncthreads();   // previous iteration's reads done before overwrite

        // Load Y slice: 80 rows x 128 halves (rows 75..79 zero), 16B chunks.
        {
            const char* yb = (const char*)g_Yh + ((size_t)c * 75 * NT + j0) * 2;
            #pragma unroll
            for (int i = tid; i < 80 * 16; i += 256) {
                int r  = i >> 4;
                int ch = i & 15;
                uint4 val = make_uint4(0u, 0u, 0u, 0u);
                if (r < 75)
                    val = *(const uint4*)(yb + (size_t)r * NT * 2 + ch * 16);
                *(uint4*)((char*)sY + (r * YST + ch * 8) * 2) = val;
            }
        }
        __syncthreads();

        float acc[2][2][4] = {};

        #pragma unroll
        for (int ks = 0; ks < 5; ++ks) {
            uint32_t ah0[4], ah1[4], al0[4], al1[4], b0[2], b1[2];
            uint32_t aoff0 = (uint32_t)(((arow)      * AST + ks * 16 + acolb) * 2);
            uint32_t aoff1 = (uint32_t)(((16 + arow) * AST + ks * 16 + acolb) * 2);
            ldm_x4(ah0, AH + aoff0);
            ldm_x4(ah1, AH + aoff1);
            ldm_x4(al0, AL + aoff0);
            ldm_x4(al1, AL + aoff1);
            uint32_t boff = (uint32_t)(((ks * 16 + brow) * YST + jw) * 2);
            ldm_x2t(b0, YS + boff);
            ldm_x2t(b1, YS + boff + 16);

            mma_f16(acc[0][0], ah0, b0);  mma_f16(acc[0][0], al0, b0);
            mma_f16(acc[0][1], ah0, b1);  mma_f16(acc[0][1], al0, b1);
            mma_f16(acc[1][0], ah1, b0);  mma_f16(acc[1][0], al1, b0);
            mma_f16(acc[1][1], ah1, b1);  mma_f16(acc[1][1], al1, b1);
        }

        // Write: lane holds rows (m*16 + r4, +8), cols jw + t*8 + q2 (+1).
        float* ob = out + (((size_t)n * CC + c) * VV) * TT + tt0;
        #pragma unroll
        for (int m = 0; m < 2; ++m)
            #pragma unroll
            for (int t = 0; t < 2; ++t) {
                int v0 = m * 16 + r4;
                int jc = jw + t * 8 + q2;
                if (v0 < VV)
                    *(float2*)(ob + (size_t)v0 * TT + jc) =
                        make_float2(acc[m][t][0], acc[m][t][1]);
                int v1 = v0 + 8;
                if (v1 < VV)
                    *(float2*)(ob + (size_t)v1 * TT + jc) =
                        make_float2(acc[m][t][2], acc[m][t][3]);
            }
    }
}

// ---------------------------------------------------------------------------
extern "C" void kernel_launch(void* const* d_in, const int* in_sizes, int n_in,
                              void* d_out, int out_size)
{
    const float* x  = (const float*)d_in[0];
    const float* Wg = (const float*)d_in[1];
    const float* Ag = (const float*)d_in[2];
    float* out = (float*)d_out;

    cudaFuncSetAttribute(stage1_mma,
                         cudaFuncAttributeMaxDynamicSharedMemorySize,
                         73728);

    dim3 g1(NT / 64, VV);             // (512, 25)
    stage1_mma<<<g1, 256, 73728>>>(x, Wg);

    dim3 g2(NT / JT, 8);              // (256, 8)
    stage2_mma<<<g2, 256>>>(Ag, out);
}

// round 8
// speedup vs baseline: 3.6040x; 1.2445x over previous
#include <cuda_runtime.h>
#include <cuda_fp16.h>
#include <cuda_bf16.h>
#include <cstdint>
#include <cstddef>

// Shapes: x[32,64,25,1024], W[25,192,64], A[3,25,25], out[32,64,25,1024]
// Stage 1 (HMMA fp16, 1 pass): Yh[c*75 + k*25 + w][j] (fp16)
//                              = sum_c' W[w, c*3+k, c'] * x[n, c', w, t]
// Stage 2 (HMMA fp16, A hi/lo): out[n,c,v,t] = sum_r A[v,r] * Yh[c*75+r][j]

#define NB 32
#define CC 64
#define VV 25
#define TT 1024
#define KK 3
#define OO (KK * CC)      /* 192 */
#define NT (NB * TT)      /* 32768 */
#define WS1 72            /* stage1 padded row stride (halves) */

typedef unsigned long long u64;

// 315 MB fp16 scratch for Y (device-global: allocation-free).
__device__ unsigned short g_Yh[(size_t)VV * OO * NT];

// ---------------------------------------------------------------------------
// helpers
// ---------------------------------------------------------------------------
__device__ __forceinline__ uint32_t smem_u32(const void* p) {
    uint32_t a;
    asm("{ .reg .u64 t; cvta.to.shared.u64 t, %1; cvt.u32.u64 %0, t; }"
        : "=r"(a) : "l"(p));
    return a;
}
__device__ __forceinline__ void ldm_x4(uint32_t a[4], uint32_t addr) {
    asm volatile("ldmatrix.sync.aligned.m8n8.x4.shared.b16 {%0,%1,%2,%3}, [%4];"
        : "=r"(a[0]), "=r"(a[1]), "=r"(a[2]), "=r"(a[3]) : "r"(addr));
}
__device__ __forceinline__ void ldm_x2t(uint32_t b[2], uint32_t addr) {
    asm volatile("ldmatrix.sync.aligned.m8n8.x2.trans.shared.b16 {%0,%1}, [%2];"
        : "=r"(b[0]), "=r"(b[1]) : "r"(addr));
}
__device__ __forceinline__ void mma_f16(float c[4], const uint32_t a[4],
                                        const uint32_t b[2]) {
    asm volatile("mma.sync.aligned.m16n8k16.row.col.f32.f16.f16.f32 "
        "{%0,%1,%2,%3}, {%4,%5,%6,%7}, {%8,%9}, {%0,%1,%2,%3};"
        : "+f"(c[0]), "+f"(c[1]), "+f"(c[2]), "+f"(c[3])
        : "r"(a[0]), "r"(a[1]), "r"(a[2]), "r"(a[3]), "r"(b[0]), "r"(b[1]));
}

// ---------------------------------------------------------------------------
// Stage 1: per (w, 64-j tile): D[192, 64] = W_w[192,64] @ X_w[64,64]
// fp16 operands, fp32 accum, single pass. Static smem 36.9 KB.
// ---------------------------------------------------------------------------
__global__ __launch_bounds__(256, 2) void stage1_mma(
    const float* __restrict__ x, const float* __restrict__ Wg)
{
    __shared__ __align__(16) __half sW[OO * WS1];   // 192 x 72
    __shared__ __align__(16) __half sX[64 * WS1];   // 64 x 72

    const uint32_t WHs = smem_u32(sW);
    const uint32_t XHs = smem_u32(sX);

    const int tid = threadIdx.x;
    const int w   = blockIdx.y;
    const int j0  = blockIdx.x * 64;
    const int n   = j0 >> 10;          // tile never crosses n
    const int t0  = j0 & 1023;

    // W[w] 192x64 fp32 -> fp16
    {
        const float* wg = Wg + (size_t)w * OO * 64;
        #pragma unroll
        for (int i = 0; i < 24; ++i) {
            int idx = tid + i * 256;       // float2 index
            int o   = idx >> 5;
            int cp  = idx & 31;
            float2 wv = *(const float2*)(wg + (size_t)o * 64 + cp * 2);
            *(__half2*)&sW[o * WS1 + cp * 2] = __floats2half2_rn(wv.x, wv.y);
        }
    }
    // X tile 64(c') x 64(j) fp32 -> fp16
    {
        const float* xb = x + (size_t)n * CC * VV * TT + (size_t)w * TT + t0;
        #pragma unroll
        for (int i = 0; i < 8; ++i) {
            int idx = tid + i * 256;
            int r   = idx >> 5;
            int cp  = idx & 31;
            float2 xv = *(const float2*)(xb + (size_t)r * (VV * TT) + cp * 2);
            *(__half2*)&sX[r * WS1 + cp * 2] = __floats2half2_rn(xv.x, xv.y);
        }
    }
    __syncthreads();

    const int wid = tid >> 5, lane = tid & 31;
    const int m0 = (wid >> 1) * 48, n0 = (wid & 1) * 32;
    const int arow = lane & 15, acolb = (lane >> 4) * 8, brow = lane & 15;

    float acc[3][4][4] = {};

    #pragma unroll
    for (int ks = 0; ks < 4; ++ks) {
        uint32_t Af[3][4], Bf[4][2];
        #pragma unroll
        for (int i = 0; i < 3; ++i)
            ldm_x4(Af[i], WHs + (uint32_t)(((m0 + 16 * i + arow) * WS1
                                            + ks * 16 + acolb) * 2));
        #pragma unroll
        for (int t = 0; t < 4; ++t)
            ldm_x2t(Bf[t], XHs + (uint32_t)(((ks * 16 + brow) * WS1
                                             + n0 + 8 * t) * 2));
        #pragma unroll
        for (int i = 0; i < 3; ++i)
            #pragma unroll
            for (int t = 0; t < 4; ++t)
                mma_f16(acc[i][t], Af[i], Bf[t]);
    }
    __syncthreads();   // all ldmatrix reads done before staging overwrites sW

    // stage D[o, jloc] as fp16 in the sW region (stride WS1)
    {
        const int r = lane >> 2, q = lane & 3;
        #pragma unroll
        for (int i = 0; i < 3; ++i)
            #pragma unroll
            for (int t = 0; t < 4; ++t) {
                int row = m0 + 16 * i + r;
                int col = n0 + 8 * t + 2 * q;
                *(half2*)((char*)sW + (row * WS1 + col) * 2) =
                    __floats2half2_rn(acc[i][t][0], acc[i][t][1]);
                *(half2*)((char*)sW + ((row + 8) * WS1 + col) * 2) =
                    __floats2half2_rn(acc[i][t][2], acc[i][t][3]);
            }
    }
    __syncthreads();

    // copy out: Y row = c*75 + k*25 + w  (c = o/3, k = o%3), 128B/row
    #pragma unroll
    for (int i = 0; i < 24; ++i) {
        int idx = tid + i * 256;
        int row = idx >> 5;               // o
        int u   = idx & 31;
        uint32_t val = *(uint32_t*)((char*)sW + row * (WS1 * 2) + u * 4);
        int cch = row / 3;
        int kk  = row - 3 * cch;
        size_t yrow = (size_t)(cch * 75 + kk * VV + w);
        *(uint32_t*)((char*)g_Yh + (yrow * NT + j0) * 2 + u * 4) = val;
    }
}

// ---------------------------------------------------------------------------
// Stage 2 (HMMA): out[v, (c,j)] = sum_r Agraph[v,r] * Yh[c*75+r][j]
// A = graph matrix [v:25->32, r:75->80] fp16 hi/lo (2 passes), built once.
// Y slice [80 r][128 j] double-buffered through registers: prefetch c+1's
// 5 x uint4 per thread while MMAing c.
// ---------------------------------------------------------------------------
#define JT  128
#define AST 88     /* A smem stride (halves) */
#define YST 136    /* Y smem stride (halves) */

__global__ __launch_bounds__(256) void stage2_mma(
    const float* __restrict__ Ag, float* __restrict__ out)
{
    __shared__ __align__(16) __half sAh[32 * AST];
    __shared__ __align__(16) __half sAl[32 * AST];
    __shared__ __align__(16) __half sY[80 * YST];

    const uint32_t AH = smem_u32(sAh);
    const uint32_t AL = smem_u32(sAl);
    const uint32_t YS = smem_u32(sY);

    const int tid = threadIdx.x;
    const int j0  = blockIdx.x * JT;
    const int c0  = blockIdx.y * 8;
    const int n   = j0 >> 10;
    const int tt0 = j0 & 1023;

    // Build graph-A hi/lo fp16 (zero-padded).
    for (int i = tid; i < 80 * 32; i += 256) {
        int r = i >> 5;
        int v = i & 31;
        float a = (r < 75 && v < 25) ? Ag[r * 25 + v] : 0.0f;
        __half h = __float2half_rn(a);
        __half l = __float2half_rn(a - __half2float(h));
        sAh[v * AST + r] = h;
        sAl[v * AST + r] = l;
    }

    const int wid  = tid >> 5, lane = tid & 31;
    const int jw   = wid * 16;
    const int arow = lane & 15, acolb = (lane >> 4) * 8;
    const int brow = lane & 15;
    const int r4   = lane >> 2, q2 = (lane & 3) * 2;

    // Per-thread slice-load coords: 5 chunks of 16B (80 rows x 16 chunks / 256).
    int lr[5], lch[5];
    #pragma unroll
    for (int s = 0; s < 5; ++s) {
        int i = tid + s * 256;
        lr[s]  = i >> 4;
        lch[s] = i & 15;
    }

    uint4 pf[5];
    // Prefetch c0 slice.
    {
        const char* yb = (const char*)g_Yh + ((size_t)c0 * 75 * NT + j0) * 2;
        #pragma unroll
        for (int s = 0; s < 5; ++s)
            pf[s] = (lr[s] < 75)
                ? *(const uint4*)(yb + (size_t)lr[s] * NT * 2 + lch[s] * 16)
                : make_uint4(0u, 0u, 0u, 0u);
    }
    __syncthreads();   // A build complete
    #pragma unroll
    for (int s = 0; s < 5; ++s)
        *(uint4*)((char*)sY + (lr[s] * YST + lch[s] * 8) * 2) = pf[s];
    __syncthreads();

    for (int ci = 0; ci < 8; ++ci) {
        const int c = c0 + ci;

        // Issue next slice's loads (overlap with MMA below).
        if (ci < 7) {
            const char* yb = (const char*)g_Yh
                           + ((size_t)(c + 1) * 75 * NT + j0) * 2;
            #pragma unroll
            for (int s = 0; s < 5; ++s)
                pf[s] = (lr[s] < 75)
                    ? *(const uint4*)(yb + (size_t)lr[s] * NT * 2 + lch[s] * 16)
                    : make_uint4(0u, 0u, 0u, 0u);
        }

        float acc[2][2][4] = {};
        #pragma unroll
        for (int ks = 0; ks < 5; ++ks) {
            uint32_t ah0[4], ah1[4], al0[4], al1[4], b0[2], b1[2];
            uint32_t aoff0 = (uint32_t)(((arow)      * AST + ks * 16 + acolb) * 2);
            uint32_t aoff1 = (uint32_t)(((16 + arow) * AST + ks * 16 + acolb) * 2);
            ldm_x4(ah0, AH + aoff0);
            ldm_x4(ah1, AH + aoff1);
            ldm_x4(al0, AL + aoff0);
            ldm_x4(al1, AL + aoff1);
            uint32_t boff = (uint32_t)(((ks * 16 + brow) * YST + jw) * 2);
            ldm_x2t(b0, YS + boff);
            ldm_x2t(b1, YS + boff + 16);

            mma_f16(acc[0][0], ah0, b0);  mma_f16(acc[0][0], al0, b0);
            mma_f16(acc[0][1], ah0, b1);  mma_f16(acc[0][1], al0, b1);
            mma_f16(acc[1][0], ah1, b0);  mma_f16(acc[1][0], al1, b0);
            mma_f16(acc[1][1], ah1, b1);  mma_f16(acc[1][1], al1, b1);
        }

        // Write output directly from fragments.
        float* ob = out + (((size_t)n * CC + c) * VV) * TT + tt0;
        #pragma unroll
        for (int m = 0; m < 2; ++m)
            #pragma unroll
            for (int t = 0; t < 2; ++t) {
                int v0 = m * 16 + r4;
                int jc = jw + t * 8 + q2;
                if (v0 < VV)
                    *(float2*)(ob + (size_t)v0 * TT + jc) =
                        make_float2(acc[m][t][0], acc[m][t][1]);
                int v1 = v0 + 8;
                if (v1 < VV)
                    *(float2*)(ob + (size_t)v1 * TT + jc) =
                        make_float2(acc[m][t][2], acc[m][t][3]);
            }

        if (ci < 7) {
            __syncthreads();   // all warps done reading sY
            #pragma unroll
            for (int s = 0; s < 5; ++s)
                *(uint4*)((char*)sY + (lr[s] * YST + lch[s] * 8) * 2) = pf[s];
            __syncthreads();
        }
    }
}

// ---------------------------------------------------------------------------
extern "C" void kernel_launch(void* const* d_in, const int* in_sizes, int n_in,
                              void* d_out, int out_size)
{
    const float* x  = (const float*)d_in[0];
    const float* Wg = (const float*)d_in[1];
    const float* Ag = (const float*)d_in[2];
    float* out = (float*)d_out;

    dim3 g1(NT / 64, VV);             // (512, 25)
    stage1_mma<<<g1, 256>>>(x, Wg);

    dim3 g2(NT / JT, 8);              // (256, 8)
    stage2_mma<<<g2, 256>>>(Ag, out);
}